// round 1
// baseline (speedup 1.0000x reference)
#include <cuda_runtime.h>
#include <cstdint>

// Problem constants (fixed shapes)
#define B    16
#define CIN  256
#define COUT 256
#define H    64
#define W    64
#define HW   (H*W)
#define EPS_F 1e-8f

// ---- scratch (static device globals; no dynamic allocation allowed) ----
__device__ float g_xs[(size_t)B*CIN*H*W];   // style-modulated input, 67MB
__device__ float g_snorm;                   // rsqrt(mean(s^2))
__device__ float g_wsq[COUT*CIN];           // sum_k w^2 per (co,ci)
__device__ float g_invwn[COUT];             // rsqrt(mean(w^2) over ci,k)
__device__ float g_scale[B*COUT];           // final per-(b,co) output scale

// ------------------------------------------------------------------
// Kernel 1: snorm = rsqrt(mean(s^2)) over all b*cin elements
// ------------------------------------------------------------------
__global__ void k_snorm(const float* __restrict__ s) {
    __shared__ float red[256];
    float acc = 0.f;
    for (int i = threadIdx.x; i < B*CIN; i += 256) {
        float v = s[i];
        acc += v * v;
    }
    red[threadIdx.x] = acc;
    __syncthreads();
    for (int off = 128; off > 0; off >>= 1) {
        if (threadIdx.x < off) red[threadIdx.x] += red[threadIdx.x + off];
        __syncthreads();
    }
    if (threadIdx.x == 0) g_snorm = rsqrtf(red[0] / (float)(B*CIN));
}

// ------------------------------------------------------------------
// Kernel 2: per-co filter stats.
//   g_wsq[co,ci]  = sum_k w[co,ci,k]^2
//   g_invwn[co]   = rsqrt(mean over (ci,k) of w^2)
// one block per co, thread = ci
// ------------------------------------------------------------------
__global__ void k_wstats(const float* __restrict__ w) {
    __shared__ float red[256];
    int co = blockIdx.x;
    int ci = threadIdx.x;
    const float* wp = w + ((size_t)co * CIN + ci) * 9;
    float s9 = 0.f;
#pragma unroll
    for (int k = 0; k < 9; k++) { float v = wp[k]; s9 += v * v; }
    g_wsq[co * CIN + ci] = s9;
    red[ci] = s9;
    __syncthreads();
    for (int off = 128; off > 0; off >>= 1) {
        if (ci < off) red[ci] += red[ci + off];
        __syncthreads();
    }
    if (ci == 0) g_invwn[co] = rsqrtf(red[0] / (float)(CIN * 9));
}

// ------------------------------------------------------------------
// Kernel 3: per-(b,co) demodulation scale.
//   sigma = invwn^2 * sum_ci (s[b,ci]*snorm)^2 * wsq[co,ci]
//   scale = invwn * rsqrt(sigma + EPS)
// grid (COUT, B), thread = ci
// ------------------------------------------------------------------
__global__ void k_scale(const float* __restrict__ s) {
    __shared__ float red[256];
    int co = blockIdx.x;
    int b  = blockIdx.y;
    int ci = threadIdx.x;
    float sn = s[b * CIN + ci] * g_snorm;
    red[ci] = sn * sn * g_wsq[co * CIN + ci];
    __syncthreads();
    for (int off = 128; off > 0; off >>= 1) {
        if (ci < off) red[ci] += red[ci + off];
        __syncthreads();
    }
    if (ci == 0) {
        float iw = g_invwn[co];
        float sigma = iw * iw * red[0];
        g_scale[b * COUT + co] = iw * rsqrtf(sigma + EPS_F);
    }
}

// ------------------------------------------------------------------
// Kernel 4: xs[b,ci,:,:] = x * (s[b,ci] * snorm)   (float4 vectorized)
// ------------------------------------------------------------------
__global__ void k_modx(const float* __restrict__ x, const float* __restrict__ s) {
    const int total4 = (B*CIN*H*W) / 4;
    float snorm = g_snorm;
    const float4* x4 = (const float4*)x;
    float4* o4 = (float4*)g_xs;
    for (int i = blockIdx.x * blockDim.x + threadIdx.x; i < total4;
         i += gridDim.x * blockDim.x) {
        int e = i * 4;               // element index
        int bc = e >> 12;            // / (H*W)  -> b*CIN + ci
        float m = s[bc] * snorm;
        float4 v = x4[i];
        v.x *= m; v.y *= m; v.z *= m; v.w *= m;
        o4[i] = v;
    }
}

// ------------------------------------------------------------------
// Kernel 5: the conv. Batch-shared weights, per-(b,co) output scale.
// Block: 64 couts x (4 rows x 64 cols). 256 threads.
// Thread: 8 couts x 4 rows x 2 cols (cols lane, lane+32).
// smem x tile: [8 ci][6 rows][68] (cols -1..64 zero-padded, pad stride)
// smem w tile: [8 ci][64 co][9]
// ------------------------------------------------------------------
#define CI_CHUNK 8
#define TCO 64
#define TROWS 4
#define XSTR 68

__global__ __launch_bounds__(256, 1)
void k_conv(const float* __restrict__ w, float* __restrict__ out) {
    __shared__ float sx[CI_CHUNK][TROWS + 2][XSTR];
    __shared__ float sw[CI_CHUNK][TCO][9];

    const int t    = threadIdx.x;
    const int lane = t & 31;
    const int wg   = t >> 5;               // 0..7 : cout subgroup
    const int r0     = blockIdx.x * TROWS; // output row base
    const int coBase = blockIdx.y * TCO;
    const int b      = blockIdx.z;

    float acc[8][4][2];
#pragma unroll
    for (int c = 0; c < 8; c++)
#pragma unroll
        for (int r = 0; r < 4; r++) { acc[c][r][0] = 0.f; acc[c][r][1] = 0.f; }

    const float* xsb = g_xs + (size_t)b * CIN * HW;

    for (int ciBase = 0; ciBase < CIN; ciBase += CI_CHUNK) {
        __syncthreads();
        // ---- load x tile (6 rows with halo, 66 cols with halo, zero pad) ----
        for (int idx = t; idx < CI_CHUNK * 6 * 66; idx += 256) {
            int c    = idx % 66;
            int rest = idx / 66;
            int r    = rest % 6;
            int ci   = rest / 6;
            int gr = r0 - 1 + r;
            int gc = c - 1;
            float v = 0.f;
            if ((unsigned)gr < (unsigned)H && (unsigned)gc < (unsigned)W)
                v = xsb[((ciBase + ci) * H + gr) * W + gc];
            sx[ci][r][c] = v;
        }
        // ---- load weight tile ----
        for (int idx = t; idx < CI_CHUNK * TCO * 9; idx += 256) {
            int k    = idx % 9;
            int rest = idx / 9;
            int co   = rest % TCO;
            int ci   = rest / TCO;
            sw[ci][co][k] =
                w[(((size_t)(coBase + co)) * CIN + (ciBase + ci)) * 9 + k];
        }
        __syncthreads();

#pragma unroll
        for (int ci = 0; ci < CI_CHUNK; ci++) {
            // x values this thread needs: 6 rows x 3 kw x 2 col-groups
            float xv[6][3][2];
#pragma unroll
            for (int r = 0; r < 6; r++)
#pragma unroll
                for (int kw = 0; kw < 3; kw++) {
                    xv[r][kw][0] = sx[ci][r][lane + kw];        // conflict-free
                    xv[r][kw][1] = sx[ci][r][lane + 32 + kw];
                }
#pragma unroll
            for (int co = 0; co < 8; co++) {
                float wv[9];
#pragma unroll
                for (int k = 0; k < 9; k++)
                    wv[k] = sw[ci][wg * 8 + co][k];             // broadcast
#pragma unroll
                for (int kh = 0; kh < 3; kh++)
#pragma unroll
                    for (int kw = 0; kw < 3; kw++) {
                        float wk = wv[kh * 3 + kw];
#pragma unroll
                        for (int r = 0; r < 4; r++) {
                            acc[co][r][0] = fmaf(wk, xv[r + kh][kw][0], acc[co][r][0]);
                            acc[co][r][1] = fmaf(wk, xv[r + kh][kw][1], acc[co][r][1]);
                        }
                    }
            }
        }
    }

    // ---- epilogue: apply per-(b,co) scale, write out ----
#pragma unroll
    for (int co = 0; co < 8; co++) {
        int gco = coBase + wg * 8 + co;
        float sc = g_scale[b * COUT + gco];
        size_t base = (((size_t)b * COUT + gco) * H + r0) * W;
#pragma unroll
        for (int r = 0; r < 4; r++) {
            out[base + (size_t)r * W + lane]      = sc * acc[co][r][0];
            out[base + (size_t)r * W + lane + 32] = sc * acc[co][r][1];
        }
    }
}

// ------------------------------------------------------------------
extern "C" void kernel_launch(void* const* d_in, const int* in_sizes, int n_in,
                              void* d_out, int out_size) {
    const float* x = (const float*)d_in[0];   // [B, CIN, H, W]
    const float* s = (const float*)d_in[1];   // [B, CIN]
    const float* w = (const float*)d_in[2];   // [COUT, CIN, 3, 3]
    float* out = (float*)d_out;               // [B, COUT, H, W]

    k_snorm<<<1, 256>>>(s);
    k_wstats<<<COUT, 256>>>(w);
    dim3 gs(COUT, B);
    k_scale<<<gs, 256>>>(s);
    k_modx<<<1024, 256>>>(x, s);
    dim3 gc(H / TROWS, COUT / TCO, B);
    k_conv<<<gc, 256>>>(w, out);
}

// round 3
// speedup vs baseline: 3.9876x; 3.9876x over previous
#include <cuda_runtime.h>
#include <cuda_bf16.h>
#include <cstdint>

// Problem constants
#define B_    16
#define CIN   256
#define COUT  256
#define H_    64
#define W_    64
#define HW_   4096
#define EPS_F 1e-8f

// ================= scratch (static device globals) =================
__device__ float g_snorm;
__device__ float g_wsq[COUT*CIN];
__device__ float g_invwn[COUT];
__device__ float g_scale[B_*COUT];
// x transposed + modulated + tf32-rounded: [b][px 4096][ci 256]
__device__ float g_xt[(size_t)B_*HW_*CIN];
// weights tf32-rounded, tap-major: [tap 9][co 256][ci 256]
__device__ float g_wt[9*COUT*CIN];

// ================= helpers =================
__device__ __forceinline__ float to_tf32(float v) {
    uint32_t r;
    asm("cvt.rna.tf32.f32 %0, %1;" : "=r"(r) : "f"(v));
    return __uint_as_float(r);
}

__device__ __forceinline__ void mma_tf32(float& d0, float& d1, float& d2, float& d3,
                                         uint32_t a0, uint32_t a1, uint32_t a2, uint32_t a3,
                                         uint32_t b0, uint32_t b1) {
    asm volatile("mma.sync.aligned.m16n8k8.row.col.f32.tf32.tf32.f32 "
                 "{%0,%1,%2,%3}, {%4,%5,%6,%7}, {%8,%9}, {%0,%1,%2,%3};"
                 : "+f"(d0), "+f"(d1), "+f"(d2), "+f"(d3)
                 : "r"(a0), "r"(a1), "r"(a2), "r"(a3), "r"(b0), "r"(b1));
}

// ================= small prep kernels =================
__global__ void k_snorm(const float* __restrict__ s) {
    __shared__ float red[256];
    float acc = 0.f;
    for (int i = threadIdx.x; i < B_*CIN; i += 256) { float v = s[i]; acc += v*v; }
    red[threadIdx.x] = acc; __syncthreads();
    for (int off = 128; off > 0; off >>= 1) {
        if (threadIdx.x < off) red[threadIdx.x] += red[threadIdx.x + off];
        __syncthreads();
    }
    if (threadIdx.x == 0) g_snorm = rsqrtf(red[0] / (float)(B_*CIN));
}

__global__ void k_wstats(const float* __restrict__ w) {
    __shared__ float red[256];
    int co = blockIdx.x, ci = threadIdx.x;
    const float* wp = w + ((size_t)co * CIN + ci) * 9;
    float s9 = 0.f;
#pragma unroll
    for (int k = 0; k < 9; k++) { float v = wp[k]; s9 += v*v; }
    g_wsq[co*CIN + ci] = s9;
    red[ci] = s9; __syncthreads();
    for (int off = 128; off > 0; off >>= 1) {
        if (ci < off) red[ci] += red[ci + off];
        __syncthreads();
    }
    if (ci == 0) g_invwn[co] = rsqrtf(red[0] / (float)(CIN*9));
}

__global__ void k_scale(const float* __restrict__ s) {
    __shared__ float red[256];
    int co = blockIdx.x, b = blockIdx.y, ci = threadIdx.x;
    float sn = s[b*CIN + ci] * g_snorm;
    red[ci] = sn*sn * g_wsq[co*CIN + ci]; __syncthreads();
    for (int off = 128; off > 0; off >>= 1) {
        if (ci < off) red[ci] += red[ci + off];
        __syncthreads();
    }
    if (ci == 0) {
        float iw = g_invwn[co];
        g_scale[b*COUT + co] = iw * rsqrtf(iw*iw*red[0] + EPS_F);
    }
}

// x -> modulated, transposed to [b][px][ci], tf32-rounded
// grid (64 pxT, 8 ciT, 16 b), 256 threads; tile 64px x 32ci
__global__ void k_prep_x(const float* __restrict__ x, const float* __restrict__ s) {
    __shared__ float sm[64][33];
    int t = threadIdx.x;
    int pxT = blockIdx.x, ciT = blockIdx.y, b = blockIdx.z;
    float snorm = g_snorm;
#pragma unroll
    for (int k = 0; k < 8; ++k) {
        int idx = k*256 + t;
        int ci = idx >> 6, px = idx & 63;
        int gci = ciT*32 + ci;
        float m = s[b*CIN + gci] * snorm;
        float v = x[(((size_t)(b*CIN + gci)) << 12) + pxT*64 + px] * m;
        sm[px][ci] = to_tf32(v);
    }
    __syncthreads();
    int px = t >> 2, q = t & 3;
    float* dst = g_xt + (((size_t)(b*HW_ + pxT*64 + px)) << 8) + ciT*32 + q*8;
#pragma unroll
    for (int e = 0; e < 8; ++e) dst[e] = sm[px][q*8 + e];
}

// weights -> [tap][co][ci], tf32-rounded. grid (256 co, 9 tap), 256 threads (ci)
__global__ void k_prep_w(const float* __restrict__ w) {
    int co = blockIdx.x, tap = blockIdx.y, ci = threadIdx.x;
    float v = w[((size_t)co * CIN + ci) * 9 + tap];
    g_wt[((size_t)(tap*COUT + co))*CIN + ci] = to_tf32(v);
}

// ================= conv: tf32 mma.sync implicit GEMM =================
// CTA tile: 64 co x 256 px (4 rows x 64 cols). 8 warps: wm(2) x wn(4),
// warp tile m32 x n64. k-chunk = 32 ci; halo x patch resident across 9 taps.
// smem: Bs[396 rows][36] (halo 6x66 px-rows, 32 ci + pad), As[2][64][36]
#define BS_ROWS  396
#define BS_STR   36
#define AS_STR   36
#define BS_FLOATS (BS_ROWS*BS_STR)           // 14256
#define AS_FLOATS (2*64*AS_STR)              // 4608
#define SMEM_FLOATS (BS_FLOATS + AS_FLOATS)  // 18864 -> 75456 B

__global__ __launch_bounds__(256, 2)
void k_conv(float* __restrict__ out) {
    extern __shared__ float smem[];
    float* Bs = smem;               // [row][k]  row = hr*66 + hc
    float* As = smem + BS_FLOATS;   // [buf][co 64][k 32 + pad]

    const int t    = threadIdx.x;
    const int lane = t & 31;
    const int wid  = t >> 5;
    const int wm   = wid >> 2;          // 0..1  (co half)
    const int wn   = wid & 3;           // 0..3  (px row)
    const int g    = lane >> 2;         // 0..7
    const int t4   = lane & 3;          // 0..3

    const int pxTile = blockIdx.x;      // 0..15 -> 4 output rows
    const int coTile = blockIdx.y;      // 0..3  -> 64 couts
    const int b      = blockIdx.z;
    const int r0     = pxTile * 4;

    float acc[2][8][4];
#pragma unroll
    for (int mi = 0; mi < 2; ++mi)
#pragma unroll
        for (int nj = 0; nj < 8; ++nj)
#pragma unroll
            for (int c = 0; c < 4; ++c) acc[mi][nj][c] = 0.f;

    const float* xb = g_xt + (((size_t)b) << 20);   // b*4096*256

    for (int chunk = 0; chunk < 8; ++chunk) {
        __syncthreads();
        // ---- load halo B patch: 6 rows x 66 cols x 32 ci, zero-padded ----
        for (int idx = t; idx < BS_ROWS * 8; idx += 256) {
            int row = idx >> 3, q = idx & 7;
            int hr = row / 66, hc = row - hr*66;
            int gr = r0 + hr - 1, gc = hc - 1;
            float4 v = make_float4(0.f, 0.f, 0.f, 0.f);
            if ((unsigned)gr < 64u && (unsigned)gc < 64u)
                v = *(const float4*)(xb + (((size_t)(gr*64 + gc)) << 8)
                                        + chunk*32 + q*4);
            float* d = Bs + row*BS_STR + q*4;
            d[0] = v.x; d[1] = v.y; d[2] = v.z; d[3] = v.w;
        }
        // ---- preload A for tap 0 into buf 0 ----
        {
            const float* wsrc = g_wt + ((size_t)(0*COUT + coTile*64))*CIN + chunk*32;
            for (int idx = t; idx < 64*8; idx += 256) {
                int row = idx >> 3, q = idx & 7;
                float4 v = *(const float4*)(wsrc + (size_t)row*CIN + q*4);
                float* d = As + row*AS_STR + q*4;
                d[0] = v.x; d[1] = v.y; d[2] = v.z; d[3] = v.w;
            }
        }
        __syncthreads();

        for (int tap = 0; tap < 9; ++tap) {
            const int cur = tap & 1;
            const int kh = tap / 3 - 1;
            const int kw = tap % 3 - 1;
            // prefetch next tap's A into other buffer
            if (tap < 8) {
                const float* wsrc = g_wt + ((size_t)((tap+1)*COUT + coTile*64))*CIN
                                  + chunk*32;
                float* abuf = As + (cur ^ 1) * (64*AS_STR);
                for (int idx = t; idx < 64*8; idx += 256) {
                    int row = idx >> 3, q = idx & 7;
                    float4 v = *(const float4*)(wsrc + (size_t)row*CIN + q*4);
                    float* d = abuf + row*AS_STR + q*4;
                    d[0] = v.x; d[1] = v.y; d[2] = v.z; d[3] = v.w;
                }
            }
            const float* A = As + cur * (64*AS_STR);
            const int hr = wn + 1 + kh;                 // 0..5
#pragma unroll
            for (int ks = 0; ks < 4; ++ks) {
                // A frags: a[mi][0..3]
                uint32_t a[2][4];
#pragma unroll
                for (int mi = 0; mi < 2; ++mi) {
                    int row = wm*32 + mi*16;
                    const float* ap = A + ks*8 + t4;
                    a[mi][0] = __float_as_uint(ap[(row + g    )*AS_STR]);
                    a[mi][1] = __float_as_uint(ap[(row + 8 + g)*AS_STR]);
                    a[mi][2] = __float_as_uint(ap[(row + g    )*AS_STR + 4]);
                    a[mi][3] = __float_as_uint(ap[(row + 8 + g)*AS_STR + 4]);
                }
                // B frags: b[nj][0..1]
                uint32_t bf[8][2];
#pragma unroll
                for (int nj = 0; nj < 8; ++nj) {
                    int hc = nj*8 + g + 1 + kw;         // 0..65
                    const float* bp = Bs + (hr*66 + hc)*BS_STR + ks*8 + t4;
                    bf[nj][0] = __float_as_uint(bp[0]);
                    bf[nj][1] = __float_as_uint(bp[4]);
                }
#pragma unroll
                for (int mi = 0; mi < 2; ++mi)
#pragma unroll
                    for (int nj = 0; nj < 8; ++nj)
                        mma_tf32(acc[mi][nj][0], acc[mi][nj][1],
                                 acc[mi][nj][2], acc[mi][nj][3],
                                 a[mi][0], a[mi][1], a[mi][2], a[mi][3],
                                 bf[nj][0], bf[nj][1]);
            }
            __syncthreads();
        }
    }

    // ---- epilogue: scale + store ----
    // D frag: c0 (row g,   col 2*t4), c1 (g, 2*t4+1), c2 (g+8, 2*t4), c3 (g+8, 2*t4+1)
#pragma unroll
    for (int mi = 0; mi < 2; ++mi) {
        int co0 = coTile*64 + wm*32 + mi*16 + g;
        int co1 = co0 + 8;
        float s0 = g_scale[b*COUT + co0];
        float s1 = g_scale[b*COUT + co1];
        float* o0 = out + (((size_t)(b*COUT + co0)) << 12) + r0*64 + wn*64;
        float* o1 = out + (((size_t)(b*COUT + co1)) << 12) + r0*64 + wn*64;
#pragma unroll
        for (int nj = 0; nj < 8; ++nj) {
            int px = nj*8 + 2*t4;
            float2 v0 = make_float2(s0*acc[mi][nj][0], s0*acc[mi][nj][1]);
            float2 v1 = make_float2(s1*acc[mi][nj][2], s1*acc[mi][nj][3]);
            *(float2*)(o0 + px) = v0;
            *(float2*)(o1 + px) = v1;
        }
    }
}

// ================= launcher =================
extern "C" void kernel_launch(void* const* d_in, const int* in_sizes, int n_in,
                              void* d_out, int out_size) {
    const float* x = (const float*)d_in[0];   // [B, CIN, H, W]
    const float* s = (const float*)d_in[1];   // [B, CIN]
    const float* w = (const float*)d_in[2];   // [COUT, CIN, 3, 3]
    float* out = (float*)d_out;               // [B, COUT, H, W]

    cudaFuncSetAttribute(k_conv, cudaFuncAttributeMaxDynamicSharedMemorySize,
                         SMEM_FLOATS * (int)sizeof(float));

    k_snorm<<<1, 256>>>(s);
    k_wstats<<<COUT, 256>>>(w);
    dim3 gs(COUT, B_);
    k_scale<<<gs, 256>>>(s);
    dim3 gw(COUT, 9);
    k_prep_w<<<gw, 256>>>(w);
    dim3 gx(64, 8, B_);
    k_prep_x<<<gx, 256>>>(x, s);
    dim3 gc(16, 4, B_);
    k_conv<<<gc, 256, SMEM_FLOATS * sizeof(float)>>>(out);
}

// round 4
// speedup vs baseline: 6.6406x; 1.6653x over previous
#include <cuda_runtime.h>
#include <cuda_fp16.h>
#include <cstdint>

// Problem constants
#define B_    16
#define CIN   256
#define COUT  256
#define H_    64
#define W_    64
#define HW_   4096
#define EPS_F 1e-8f

// ================= scratch (static device globals) =================
__device__ float g_snorm;
__device__ float g_wsq[COUT*CIN];
__device__ float g_invwn[COUT];
__device__ float g_scale[B_*COUT];
// x transposed + modulated, fp16: [b][px 4096][ci 256]
__device__ __align__(16) __half g_xh[(size_t)B_*HW_*CIN];
// weights fp16, tap-major: [tap 9][co 256][ci 256]
__device__ __align__(16) __half g_wh[9*COUT*CIN];

// ================= helpers =================
__device__ __forceinline__ void mma_fp16(float& d0, float& d1, float& d2, float& d3,
                                         uint32_t a0, uint32_t a1, uint32_t a2, uint32_t a3,
                                         uint32_t b0, uint32_t b1) {
    asm volatile("mma.sync.aligned.m16n8k16.row.col.f32.f16.f16.f32 "
                 "{%0,%1,%2,%3}, {%4,%5,%6,%7}, {%8,%9}, {%0,%1,%2,%3};"
                 : "+f"(d0), "+f"(d1), "+f"(d2), "+f"(d3)
                 : "r"(a0), "r"(a1), "r"(a2), "r"(a3), "r"(b0), "r"(b1));
}

// ================= small prep kernels =================
__global__ void k_snorm(const float* __restrict__ s) {
    __shared__ float red[256];
    float acc = 0.f;
    for (int i = threadIdx.x; i < B_*CIN; i += 256) { float v = s[i]; acc += v*v; }
    red[threadIdx.x] = acc; __syncthreads();
    for (int off = 128; off > 0; off >>= 1) {
        if (threadIdx.x < off) red[threadIdx.x] += red[threadIdx.x + off];
        __syncthreads();
    }
    if (threadIdx.x == 0) g_snorm = rsqrtf(red[0] / (float)(B_*CIN));
}

__global__ void k_wstats(const float* __restrict__ w) {
    __shared__ float red[256];
    int co = blockIdx.x, ci = threadIdx.x;
    const float* wp = w + ((size_t)co * CIN + ci) * 9;
    float s9 = 0.f;
#pragma unroll
    for (int k = 0; k < 9; k++) { float v = wp[k]; s9 += v*v; }
    g_wsq[co*CIN + ci] = s9;
    red[ci] = s9; __syncthreads();
    for (int off = 128; off > 0; off >>= 1) {
        if (ci < off) red[ci] += red[ci + off];
        __syncthreads();
    }
    if (ci == 0) g_invwn[co] = rsqrtf(red[0] / (float)(CIN*9));
}

__global__ void k_scale(const float* __restrict__ s) {
    __shared__ float red[256];
    int co = blockIdx.x, b = blockIdx.y, ci = threadIdx.x;
    float sn = s[b*CIN + ci] * g_snorm;
    red[ci] = sn*sn * g_wsq[co*CIN + ci]; __syncthreads();
    for (int off = 128; off > 0; off >>= 1) {
        if (ci < off) red[ci] += red[ci + off];
        __syncthreads();
    }
    if (ci == 0) {
        float iw = g_invwn[co];
        g_scale[b*COUT + co] = iw * rsqrtf(iw*iw*red[0] + EPS_F);
    }
}

// x -> modulated, transposed to [b][px][ci], fp16
// grid (64 pxT, 8 ciT, 16 b), 256 threads; tile 64px x 32ci
__global__ void k_prep_x(const float* __restrict__ x, const float* __restrict__ s) {
    __shared__ __half sm[64][40];
    int t = threadIdx.x;
    int pxT = blockIdx.x, ciT = blockIdx.y, b = blockIdx.z;
    float snorm = g_snorm;
#pragma unroll
    for (int k = 0; k < 8; ++k) {
        int idx = k*256 + t;
        int ci = idx >> 6, px = idx & 63;
        int gci = ciT*32 + ci;
        float m = s[b*CIN + gci] * snorm;
        float v = x[(((size_t)(b*CIN + gci)) << 12) + pxT*64 + px] * m;
        sm[px][ci] = __float2half_rn(v);
    }
    __syncthreads();
    int px = t >> 2, q = t & 3;
    size_t o = (((size_t)(b*HW_ + pxT*64 + px)) << 8) + ciT*32 + q*8;
    *(uint4*)(g_xh + o) = *(const uint4*)&sm[px][q*8];
}

// weights -> [tap][co][ci], fp16. grid (256 co, 9 tap), 256 threads (ci)
__global__ void k_prep_w(const float* __restrict__ w) {
    int co = blockIdx.x, tap = blockIdx.y, ci = threadIdx.x;
    float v = w[((size_t)co * CIN + ci) * 9 + tap];
    g_wh[((size_t)(tap*COUT + co))*CIN + ci] = __float2half_rn(v);
}

// ================= conv: fp16 mma.sync implicit GEMM =================
// CTA tile: 64 co x 256 px (4 rows x 64 cols). 8 warps: wm(2) x wn(4),
// warp tile m32 x n64, k16 per MMA (32-ci chunk = 2 k-steps).
// smem halves: Bs[396 rows][40] (halo 6x66 px-rows, 32 ci + pad), As[2][64][40]
#define BS_ROWS  396
#define BS_STR   40
#define AS_STR   40
#define BS_HALVES (BS_ROWS*BS_STR)            // 15840
#define AS_HALVES (2*64*AS_STR)               // 5120
#define SMEM_BYTES ((BS_HALVES + AS_HALVES)*2) // 41920

__global__ __launch_bounds__(256, 2)
void k_conv(float* __restrict__ out) {
    extern __shared__ __half smem[];
    __half* Bs = smem;               // [row 0..395][k 0..31 + pad]
    __half* As = smem + BS_HALVES;   // [buf][co 64][k 32 + pad]

    const int t    = threadIdx.x;
    const int lane = t & 31;
    const int wid  = t >> 5;
    const int wm   = wid >> 2;          // 0..1  (co half)
    const int wn   = wid & 3;           // 0..3  (px row)
    const int g    = lane >> 2;         // 0..7
    const int t4   = lane & 3;          // 0..3

    const int pxTile = blockIdx.x;      // 0..15 -> 4 output rows
    const int coTile = blockIdx.y;      // 0..3  -> 64 couts
    const int b      = blockIdx.z;
    const int r0     = pxTile * 4;

    float acc[2][8][4];
#pragma unroll
    for (int mi = 0; mi < 2; ++mi)
#pragma unroll
        for (int nj = 0; nj < 8; ++nj)
#pragma unroll
            for (int c = 0; c < 4; ++c) acc[mi][nj][c] = 0.f;

    const __half* xb = g_xh + (((size_t)b) << 20);   // b*4096*256

    for (int chunk = 0; chunk < 8; ++chunk) {
        __syncthreads();
        // ---- load halo B patch: 6 rows x 66 cols x 32 ci fp16, zero-padded ----
        for (int idx = t; idx < BS_ROWS * 4; idx += 256) {
            int row = idx >> 2, q = idx & 3;
            int hr = row / 66, hc = row - hr*66;
            int gr = r0 + hr - 1, gc = hc - 1;
            uint4 v = make_uint4(0u, 0u, 0u, 0u);
            if ((unsigned)gr < 64u && (unsigned)gc < 64u)
                v = *(const uint4*)(xb + (((size_t)(gr*64 + gc)) << 8)
                                       + chunk*32 + q*8);
            *(uint4*)(Bs + row*BS_STR + q*8) = v;
        }
        // ---- preload A for tap 0 into buf 0 ----
        {
            const __half* wsrc = g_wh + ((size_t)(coTile*64))*CIN + chunk*32;
            for (int idx = t; idx < 64*4; idx += 256) {
                int row = idx >> 2, q = idx & 3;
                *(uint4*)(As + row*AS_STR + q*8) =
                    *(const uint4*)(wsrc + (size_t)row*CIN + q*8);
            }
        }
        __syncthreads();

        for (int tap = 0; tap < 9; ++tap) {
            const int cur = tap & 1;
            const int kh = tap / 3 - 1;
            const int kw = tap % 3 - 1;
            // prefetch next tap's A into other buffer
            if (tap < 8) {
                const __half* wsrc = g_wh + ((size_t)((tap+1)*COUT + coTile*64))*CIN
                                  + chunk*32;
                __half* abuf = As + (cur ^ 1) * (64*AS_STR);
                for (int idx = t; idx < 64*4; idx += 256) {
                    int row = idx >> 2, q = idx & 3;
                    *(uint4*)(abuf + row*AS_STR + q*8) =
                        *(const uint4*)(wsrc + (size_t)row*CIN + q*8);
                }
            }
            const __half* A = As + cur * (64*AS_STR);
            const int hr = wn + 1 + kh;                 // 0..5
#pragma unroll
            for (int ks = 0; ks < 2; ++ks) {
                // A frags (packed half2 via b32 loads)
                uint32_t a[2][4];
#pragma unroll
                for (int mi = 0; mi < 2; ++mi) {
                    const __half* ap = A + (wm*32 + mi*16 + g)*AS_STR
                                     + ks*16 + 2*t4;
                    a[mi][0] = *(const uint32_t*)(ap);
                    a[mi][1] = *(const uint32_t*)(ap + 8*AS_STR);
                    a[mi][2] = *(const uint32_t*)(ap + 8);
                    a[mi][3] = *(const uint32_t*)(ap + 8*AS_STR + 8);
                }
                // B frags
                uint32_t bf[8][2];
#pragma unroll
                for (int nj = 0; nj < 8; ++nj) {
                    int hc = nj*8 + g + 1 + kw;         // 0..65
                    const __half* bp = Bs + (hr*66 + hc)*BS_STR + ks*16 + 2*t4;
                    bf[nj][0] = *(const uint32_t*)(bp);
                    bf[nj][1] = *(const uint32_t*)(bp + 8);
                }
#pragma unroll
                for (int mi = 0; mi < 2; ++mi)
#pragma unroll
                    for (int nj = 0; nj < 8; ++nj)
                        mma_fp16(acc[mi][nj][0], acc[mi][nj][1],
                                 acc[mi][nj][2], acc[mi][nj][3],
                                 a[mi][0], a[mi][1], a[mi][2], a[mi][3],
                                 bf[nj][0], bf[nj][1]);
            }
            __syncthreads();
        }
    }

    // ---- epilogue: scale + store ----
    // D frag: c0 (row g, col 2t4), c1 (g, 2t4+1), c2 (g+8, 2t4), c3 (g+8, 2t4+1)
#pragma unroll
    for (int mi = 0; mi < 2; ++mi) {
        int co0 = coTile*64 + wm*32 + mi*16 + g;
        int co1 = co0 + 8;
        float s0 = g_scale[b*COUT + co0];
        float s1 = g_scale[b*COUT + co1];
        float* o0 = out + (((size_t)(b*COUT + co0)) << 12) + r0*64 + wn*64;
        float* o1 = out + (((size_t)(b*COUT + co1)) << 12) + r0*64 + wn*64;
#pragma unroll
        for (int nj = 0; nj < 8; ++nj) {
            int px = nj*8 + 2*t4;
            *(float2*)(o0 + px) = make_float2(s0*acc[mi][nj][0], s0*acc[mi][nj][1]);
            *(float2*)(o1 + px) = make_float2(s1*acc[mi][nj][2], s1*acc[mi][nj][3]);
        }
    }
}

// ================= launcher =================
extern "C" void kernel_launch(void* const* d_in, const int* in_sizes, int n_in,
                              void* d_out, int out_size) {
    const float* x = (const float*)d_in[0];   // [B, CIN, H, W]
    const float* s = (const float*)d_in[1];   // [B, CIN]
    const float* w = (const float*)d_in[2];   // [COUT, CIN, 3, 3]
    float* out = (float*)d_out;               // [B, COUT, H, W]

    cudaFuncSetAttribute(k_conv, cudaFuncAttributeMaxDynamicSharedMemorySize,
                         SMEM_BYTES);

    k_snorm<<<1, 256>>>(s);
    k_wstats<<<COUT, 256>>>(w);
    dim3 gs(COUT, B_);
    k_scale<<<gs, 256>>>(s);
    dim3 gw(COUT, 9);
    k_prep_w<<<gw, 256>>>(w);
    dim3 gx(64, 8, B_);
    k_prep_x<<<gx, 256>>>(x, s);
    dim3 gc(16, 4, B_);
    k_conv<<<gc, 256, SMEM_BYTES>>>(out);
}